// round 12
// baseline (speedup 1.0000x reference)
#include <cuda_runtime.h>
#include <cuda_fp16.h>
#include <cstdint>

// ============================================================================
// EdgeMLP: f = MLP(edges[:, :3]); out[i][j] = (cls1[i]==cls2[j]) * cos(f1[i],f2[j])
// Round 12: R11 barrier-free strip with IT=4 (grid 4096) to kill the
// wave-quantization tail (3.46 waves -> 6.92 waves, ceil 7, ~1% loss).
// ============================================================================

#define N_MAX 8192
#define KK 32

__device__ __half g_h1[N_MAX * KK];
__device__ __half g_h2[N_MAX * KK];
__device__ int    g_c1[N_MAX];
__device__ int    g_c2[N_MAX];

// ----------------------------------------------------------------------------
// Kernel 1: MLP + normalize, 4 threads per row (each 8 of 32 outputs).
// ----------------------------------------------------------------------------
__global__ void __launch_bounds__(256) feat_kernel(
    const float* __restrict__ e1, const float* __restrict__ e2, int N1, int N2,
    const float* __restrict__ W1, const float* __restrict__ b1,
    const float* __restrict__ W2, const float* __restrict__ b2)
{
    __shared__ float sW1[192], sb1[64], sW2[2048], sb2[32];
    int t = threadIdx.x;
    for (int i = t; i < 192;  i += 256) sW1[i] = W1[i];
    if (t < 64) sb1[t] = b1[t];
    for (int i = t; i < 2048; i += 256) sW2[i] = W2[i];
    if (t < 32) sb2[t] = b2[t];
    __syncthreads();

    int gid  = blockIdx.x * 256 + t;
    int row2 = gid >> 2;
    int s    = gid & 3;
    if (row2 >= N1 + N2) return;

    const float* ed; __half* fo; int* co; int row;
    if (row2 < N1) { ed = e1; fo = g_h1; co = g_c1; row = row2; }
    else           { ed = e2; fo = g_h2; co = g_c2; row = row2 - N1; }

    float4 e = reinterpret_cast<const float4*>(ed)[row];

    float f[8];
    #pragma unroll
    for (int q = 0; q < 8; q++) f[q] = sb2[s * 8 + q];

    #pragma unroll 8
    for (int k = 0; k < 64; k++) {
        float h = fmaf(e.x, sW1[k], fmaf(e.y, sW1[64 + k], fmaf(e.z, sW1[128 + k], sb1[k])));
        h = fmaxf(h, 0.0f);
        const float4* w = reinterpret_cast<const float4*>(&sW2[k * 32 + s * 8]);
        float4 w0 = w[0], w1 = w[1];
        f[0] = fmaf(h, w0.x, f[0]); f[1] = fmaf(h, w0.y, f[1]);
        f[2] = fmaf(h, w0.z, f[2]); f[3] = fmaf(h, w0.w, f[3]);
        f[4] = fmaf(h, w1.x, f[4]); f[5] = fmaf(h, w1.y, f[5]);
        f[6] = fmaf(h, w1.z, f[6]); f[7] = fmaf(h, w1.w, f[7]);
    }

    float p = 0.0f;
    #pragma unroll
    for (int q = 0; q < 8; q++) p = fmaf(f[q], f[q], p);
    p += __shfl_xor_sync(0xFFFFFFFFu, p, 1);
    p += __shfl_xor_sync(0xFFFFFFFFu, p, 2);
    float inv = rsqrtf(fmaxf(p, 1e-24f));

    __half2 o[4];
    #pragma unroll
    for (int q = 0; q < 4; q++)
        o[q] = __floats2half2_rn(f[2 * q] * inv, f[2 * q + 1] * inv);
    *reinterpret_cast<uint4*>(fo + (size_t)row * KK + s * 8) = *reinterpret_cast<uint4*>(o);
    if (s == 0) co[row] = (int)e.w;
}

// ----------------------------------------------------------------------------
__device__ __forceinline__ void hmma(float c[4], const uint32_t a[4], const uint32_t b[2]) {
    asm volatile(
        "mma.sync.aligned.m16n8k16.row.col.f32.f16.f16.f32 "
        "{%0,%1,%2,%3}, {%4,%5,%6,%7}, {%8,%9}, {%0,%1,%2,%3};"
        : "+f"(c[0]), "+f"(c[1]), "+f"(c[2]), "+f"(c[3])
        : "r"(a[0]), "r"(a[1]), "r"(a[2]), "r"(a[3]), "r"(b[0]), "r"(b[1]));
}

__device__ __forceinline__ void stg256(float* p, const float v[8]) {
    asm volatile(
        "st.global.v8.b32 [%0], {%1,%2,%3,%4,%5,%6,%7,%8};"
        :: "l"(p),
           "r"(__float_as_uint(v[0])), "r"(__float_as_uint(v[1])),
           "r"(__float_as_uint(v[2])), "r"(__float_as_uint(v[3])),
           "r"(__float_as_uint(v[4])), "r"(__float_as_uint(v[5])),
           "r"(__float_as_uint(v[6])), "r"(__float_as_uint(v[7]))
        : "memory");
}

__device__ __forceinline__ void cp_async16(uint32_t smem_dst, const void* gsrc) {
    asm volatile("cp.async.cg.shared.global [%0], [%1], 16;" :: "r"(smem_dst), "l"(gsrc));
}
#define CP_COMMIT() asm volatile("cp.async.commit_group;")
#define CP_WAIT0()  asm volatile("cp.async.wait_group 0;")

// Column permutation within each 32-col slab: global col j = 8q + 2*nt + e
// lives at smem slab row r = nt*8 + 2q + e  =>  thread q owns 8 contiguous
// global output columns, enabling masked STG.256.
__device__ __forceinline__ int bperm_row(int j) {
    int jl = j & 31;
    int r  = ((jl >> 1) & 3) * 8 + ((jl >> 3) & 3) * 2 + (jl & 1);
    return (j & ~31) + r;
}

// ----------------------------------------------------------------------------
// Kernel 2: strip of IT subtiles (32 rows x 128 cols) per CTA, barrier-free
// main loop. 256 threads = 8 warps (2 M x 4 N), warp subtile 16x32.
// ----------------------------------------------------------------------------
#define RS 40   // smem row stride in halves (80B)
#define IT 4    // i-subtiles per CTA strip (128 rows) -> grid 4096, ~7 waves

__global__ void __launch_bounds__(256, 4) pair_kernel(float* __restrict__ out, int N2)
{
    __shared__ __half Bs[128][RS];        // B tile (permuted), read once

    int t    = threadIdx.x;
    int wid  = t >> 5;
    int lane = t & 31;
    int j0   = blockIdx.x * 128;
    int i0   = blockIdx.y * (32 * IT);

    // --- Prologue: cp.async B (permuted) ---
    #pragma unroll
    for (int p = 0; p < 2; p++) {
        int v = t + p * 256;
        int row = v >> 2, c16 = v & 3;
        uint32_t dst = (uint32_t)__cvta_generic_to_shared(&Bs[bperm_row(row)][c16 * 8]);
        cp_async16(dst, (const char*)(g_h2 + (size_t)(j0 + row) * KK) + c16 * 16);
    }
    CP_COMMIT();

    int warp_m = wid >> 2;     // 0..1
    int warp_n = wid & 3;      // 0..3
    int r4 = lane >> 2;        // 0..7
    int q  = lane & 3;         // 0..3
    int c2 = q * 2;

    // Class LUT: bit (c*8 + v) set iff column v's class == c (classes 0..7).
    int cb = warp_n * 32 + 8 * q;
    unsigned long long lut = 0ULL;
    #pragma unroll
    for (int v = 0; v < 8; v++) {
        int c = g_c2[j0 + cb + v] & 7;
        lut |= 1ULL << (c * 8 + v);
    }

    CP_WAIT0();
    __syncthreads();           // the ONLY barrier

    // --- Hoist B fragments into registers (reused for all IT subtiles) ---
    uint32_t bf[2][4][2];
    #pragma unroll
    for (int k = 0; k < 2; k++) {
        int kc = c2 + k * 16;
        #pragma unroll
        for (int nt = 0; nt < 4; nt++) {
            int col = warp_n * 32 + nt * 8 + r4;
            bf[k][nt][0] = *reinterpret_cast<const uint32_t*>(&Bs[col][kc    ]);
            bf[k][nt][1] = *reinterpret_cast<const uint32_t*>(&Bs[col][kc + 8]);
        }
    }

    int rA = warp_m * 16 + r4;                         // rows rA, rA+8 in subtile
    const uint32_t* a32 = reinterpret_cast<const uint32_t*>(g_h1);   // 2 halves per u32
    float* rowPtrA = out + (size_t)(i0 + rA)     * (size_t)N2 + (size_t)(j0 + cb);
    float* rowPtrB = out + (size_t)(i0 + rA + 8) * (size_t)N2 + (size_t)(j0 + cb);
    size_t stepOut = (size_t)32 * (size_t)N2;

    #pragma unroll
    for (int it = 0; it < IT; it++) {
        int rg0 = i0 + it * 32 + rA;       // global row of first A row
        // A fragments direct from global (L1-hit heavy: 2KB subtile / 4 warps share)
        const uint32_t* aRow0 = a32 + (size_t)rg0 * 16 + q;        // [row][q*2] halves
        const uint32_t* aRow1 = aRow0 + 8 * 16;                    // row + 8

        float acc[4][4];
        #pragma unroll
        for (int nt = 0; nt < 4; nt++)
            #pragma unroll
            for (int v = 0; v < 4; v++) acc[nt][v] = 0.0f;

        #pragma unroll
        for (int k = 0; k < 2; k++) {
            uint32_t af[4];
            af[0] = __ldg(aRow0 + k * 8);          // (rA,   kc)
            af[1] = __ldg(aRow1 + k * 8);          // (rA+8, kc)
            af[2] = __ldg(aRow0 + k * 8 + 4);      // (rA,   kc+8)
            af[3] = __ldg(aRow1 + k * 8 + 4);      // (rA+8, kc+8)
            #pragma unroll
            for (int nt = 0; nt < 4; nt++)
                hmma(acc[nt], af, bf[k][nt]);
        }

        // Row classes (broadcast loads) -> 8-bit masks from LUT
        int cmA = g_c1[rg0]     & 7;
        int cmB = g_c1[rg0 + 8] & 7;
        unsigned mA = (unsigned)(lut >> (cmA * 8)) & 0xFFu;
        unsigned mB = (unsigned)(lut >> (cmB * 8)) & 0xFFu;

        float va[8], vb[8];
        #pragma unroll
        for (int nt = 0; nt < 4; nt++) {
            va[2 * nt]     = (mA & (1u << (2 * nt)))     ? acc[nt][0] : 0.0f;
            va[2 * nt + 1] = (mA & (1u << (2 * nt + 1))) ? acc[nt][1] : 0.0f;
            vb[2 * nt]     = (mB & (1u << (2 * nt)))     ? acc[nt][2] : 0.0f;
            vb[2 * nt + 1] = (mB & (1u << (2 * nt + 1))) ? acc[nt][3] : 0.0f;
        }
        stg256(rowPtrA, va);
        stg256(rowPtrB, vb);
        rowPtrA += stepOut;
        rowPtrB += stepOut;
    }
}

// ----------------------------------------------------------------------------
extern "C" void kernel_launch(void* const* d_in, const int* in_sizes, int n_in,
                              void* d_out, int out_size)
{
    const float* edges1 = (const float*)d_in[0];
    const float* edges2 = (const float*)d_in[1];
    const float* W1     = (const float*)d_in[2];
    const float* b1     = (const float*)d_in[3];
    const float* W2     = (const float*)d_in[4];
    const float* b2     = (const float*)d_in[5];
    float* out = (float*)d_out;

    int N1 = in_sizes[0] / 4;
    int N2 = in_sizes[1] / 4;

    int totalThreads = (N1 + N2) * 4;
    feat_kernel<<<(totalThreads + 255) / 256, 256>>>(edges1, edges2, N1, N2, W1, b1, W2, b2);

    dim3 grid(N2 / 128, N1 / (32 * IT));
    pair_kernel<<<grid, 256>>>(out, N2);
}

// round 13
// speedup vs baseline: 1.0364x; 1.0364x over previous
#include <cuda_runtime.h>
#include <cuda_fp16.h>
#include <cstdint>

// ============================================================================
// EdgeMLP: f = MLP(edges[:, :3]); out[i][j] = (cls1[i]==cls2[j]) * cos(f1[i],f2[j])
// Round 13: R11 + A rows stored PRE-PERMUTED by feat_kernel so each pair-kernel
// thread fetches its full A fragment set for a row with ONE LDG.128
// (u32 j = q+4i stored at position 4q+i). A-path L1 wavefronts drop 4x.
// ============================================================================

#define N_MAX 8192
#define KK 32

__device__ __half g_h1[N_MAX * KK];   // A features, per-row u32-permuted
__device__ __half g_h2[N_MAX * KK];   // B features, natural layout
__device__ int    g_c1[N_MAX];
__device__ int    g_c2[N_MAX];

// ----------------------------------------------------------------------------
// Kernel 1: MLP + normalize, 4 threads per row (each 8 of 32 outputs).
// A-side rows are written permuted: original u32 index (s + 4i) -> pos (4s + i).
// ----------------------------------------------------------------------------
__global__ void __launch_bounds__(256) feat_kernel(
    const float* __restrict__ e1, const float* __restrict__ e2, int N1, int N2,
    const float* __restrict__ W1, const float* __restrict__ b1,
    const float* __restrict__ W2, const float* __restrict__ b2)
{
    __shared__ float sW1[192], sb1[64], sW2[2048], sb2[32];
    int t = threadIdx.x;
    for (int i = t; i < 192;  i += 256) sW1[i] = W1[i];
    if (t < 64) sb1[t] = b1[t];
    for (int i = t; i < 2048; i += 256) sW2[i] = W2[i];
    if (t < 32) sb2[t] = b2[t];
    __syncthreads();

    int gid  = blockIdx.x * 256 + t;
    int row2 = gid >> 2;
    int s    = gid & 3;
    if (row2 >= N1 + N2) return;

    bool isA = (row2 < N1);
    const float* ed = isA ? e1 : e2;
    int row = isA ? row2 : row2 - N1;

    float4 e = reinterpret_cast<const float4*>(ed)[row];

    float f[8];
    #pragma unroll
    for (int q = 0; q < 8; q++) f[q] = sb2[s * 8 + q];

    #pragma unroll 8
    for (int k = 0; k < 64; k++) {
        float h = fmaf(e.x, sW1[k], fmaf(e.y, sW1[64 + k], fmaf(e.z, sW1[128 + k], sb1[k])));
        h = fmaxf(h, 0.0f);
        const float4* w = reinterpret_cast<const float4*>(&sW2[k * 32 + s * 8]);
        float4 w0 = w[0], w1 = w[1];
        f[0] = fmaf(h, w0.x, f[0]); f[1] = fmaf(h, w0.y, f[1]);
        f[2] = fmaf(h, w0.z, f[2]); f[3] = fmaf(h, w0.w, f[3]);
        f[4] = fmaf(h, w1.x, f[4]); f[5] = fmaf(h, w1.y, f[5]);
        f[6] = fmaf(h, w1.z, f[6]); f[7] = fmaf(h, w1.w, f[7]);
    }

    float p = 0.0f;
    #pragma unroll
    for (int q = 0; q < 8; q++) p = fmaf(f[q], f[q], p);
    p += __shfl_xor_sync(0xFFFFFFFFu, p, 1);
    p += __shfl_xor_sync(0xFFFFFFFFu, p, 2);
    float inv = rsqrtf(fmaxf(p, 1e-24f));

    uint32_t o[4];
    #pragma unroll
    for (int q = 0; q < 4; q++) {
        __half2 h2 = __floats2half2_rn(f[2 * q] * inv, f[2 * q + 1] * inv);
        o[q] = *reinterpret_cast<uint32_t*>(&h2);
    }

    if (isA) {
        // permuted scatter: original u32 (s + 4i) -> position (4s + i)... inverse:
        // this thread holds original u32s j = 4s + i; dest pos = 4*(j%4) + (j/4)
        // j = 4s+i -> q' = i, i' = s  => pos = 4i + s
        uint32_t* dst = reinterpret_cast<uint32_t*>(g_h1) + (size_t)row * 16;
        #pragma unroll
        for (int i = 0; i < 4; i++) dst[4 * i + s] = o[i];
        if (s == 0) g_c1[row] = (int)e.w;
    } else {
        *reinterpret_cast<uint4*>(g_h2 + (size_t)row * KK + s * 8) =
            *reinterpret_cast<uint4*>(o);
        if (s == 0) g_c2[row] = (int)e.w;
    }
}

// ----------------------------------------------------------------------------
__device__ __forceinline__ void hmma(float c[4], const uint32_t a[4], const uint32_t b[2]) {
    asm volatile(
        "mma.sync.aligned.m16n8k16.row.col.f32.f16.f16.f32 "
        "{%0,%1,%2,%3}, {%4,%5,%6,%7}, {%8,%9}, {%0,%1,%2,%3};"
        : "+f"(c[0]), "+f"(c[1]), "+f"(c[2]), "+f"(c[3])
        : "r"(a[0]), "r"(a[1]), "r"(a[2]), "r"(a[3]), "r"(b[0]), "r"(b[1]));
}

__device__ __forceinline__ void stg256(float* p, const float v[8]) {
    asm volatile(
        "st.global.v8.b32 [%0], {%1,%2,%3,%4,%5,%6,%7,%8};"
        :: "l"(p),
           "r"(__float_as_uint(v[0])), "r"(__float_as_uint(v[1])),
           "r"(__float_as_uint(v[2])), "r"(__float_as_uint(v[3])),
           "r"(__float_as_uint(v[4])), "r"(__float_as_uint(v[5])),
           "r"(__float_as_uint(v[6])), "r"(__float_as_uint(v[7]))
        : "memory");
}

__device__ __forceinline__ void cp_async16(uint32_t smem_dst, const void* gsrc) {
    asm volatile("cp.async.cg.shared.global [%0], [%1], 16;" :: "r"(smem_dst), "l"(gsrc));
}
#define CP_COMMIT() asm volatile("cp.async.commit_group;")
#define CP_WAIT0()  asm volatile("cp.async.wait_group 0;")

// B column permutation within each 32-col slab (see R5-R7): thread q owns 8
// contiguous global output columns, enabling masked STG.256.
__device__ __forceinline__ int bperm_row(int j) {
    int jl = j & 31;
    int r  = ((jl >> 1) & 3) * 8 + ((jl >> 3) & 3) * 2 + (jl & 1);
    return (j & ~31) + r;
}

// ----------------------------------------------------------------------------
// Kernel 2: strip of IT subtiles (32 rows x 128 cols) per CTA, barrier-free
// main loop. 256 threads = 8 warps (2 M x 4 N), warp subtile 16x32.
// ----------------------------------------------------------------------------
#define RS 40   // smem row stride in halves (80B)
#define IT 8    // i-subtiles per CTA strip

__global__ void __launch_bounds__(256, 4) pair_kernel(float* __restrict__ out, int N2)
{
    __shared__ __half Bs[128][RS];        // B tile (permuted), read once

    int t    = threadIdx.x;
    int wid  = t >> 5;
    int lane = t & 31;
    int j0   = blockIdx.x * 128;
    int i0   = blockIdx.y * (32 * IT);

    // --- Prologue: cp.async B (permuted) ---
    #pragma unroll
    for (int p = 0; p < 2; p++) {
        int v = t + p * 256;
        int row = v >> 2, c16 = v & 3;
        uint32_t dst = (uint32_t)__cvta_generic_to_shared(&Bs[bperm_row(row)][c16 * 8]);
        cp_async16(dst, (const char*)(g_h2 + (size_t)(j0 + row) * KK) + c16 * 16);
    }
    CP_COMMIT();

    int warp_m = wid >> 2;     // 0..1
    int warp_n = wid & 3;      // 0..3
    int r4 = lane >> 2;        // 0..7
    int q  = lane & 3;         // 0..3
    int c2 = q * 2;

    // Class LUT: bit (c*8 + v) set iff column v's class == c (classes 0..7).
    int cb = warp_n * 32 + 8 * q;
    unsigned long long lut = 0ULL;
    #pragma unroll
    for (int v = 0; v < 8; v++) {
        int c = g_c2[j0 + cb + v] & 7;
        lut |= 1ULL << (c * 8 + v);
    }

    CP_WAIT0();
    __syncthreads();           // the ONLY barrier

    // --- Hoist B fragments into registers (reused for all IT subtiles) ---
    uint32_t bf[2][4][2];
    #pragma unroll
    for (int k = 0; k < 2; k++) {
        int kc = c2 + k * 16;
        #pragma unroll
        for (int nt = 0; nt < 4; nt++) {
            int col = warp_n * 32 + nt * 8 + r4;
            bf[k][nt][0] = *reinterpret_cast<const uint32_t*>(&Bs[col][kc    ]);
            bf[k][nt][1] = *reinterpret_cast<const uint32_t*>(&Bs[col][kc + 8]);
        }
    }

    int rA = warp_m * 16 + r4;                         // rows rA, rA+8 in subtile
    const uint4* a128 = reinterpret_cast<const uint4*>(g_h1);   // 4 uint4 per row
    float* rowPtrA = out + (size_t)(i0 + rA)     * (size_t)N2 + (size_t)(j0 + cb);
    float* rowPtrB = out + (size_t)(i0 + rA + 8) * (size_t)N2 + (size_t)(j0 + cb);
    size_t stepOut = (size_t)32 * (size_t)N2;

    #pragma unroll
    for (int it = 0; it < IT; it++) {
        int rg0 = i0 + it * 32 + rA;       // global row of first A row

        // ONE LDG.128 per A row: permuted layout puts {kc, kc+8, kc+16, kc+24}
        // fragments for thread q contiguously at uint4 slot q.
        uint4 A0 = __ldg(&a128[(size_t)rg0 * 4 + q]);
        uint4 A1 = __ldg(&a128[(size_t)(rg0 + 8) * 4 + q]);

        float acc[4][4];
        #pragma unroll
        for (int nt = 0; nt < 4; nt++)
            #pragma unroll
            for (int v = 0; v < 4; v++) acc[nt][v] = 0.0f;

        {   // k = 0: af = {(rA,kc),(rA+8,kc),(rA,kc+8),(rA+8,kc+8)}
            uint32_t af[4] = { A0.x, A1.x, A0.y, A1.y };
            #pragma unroll
            for (int nt = 0; nt < 4; nt++)
                hmma(acc[nt], af, bf[0][nt]);
        }
        {   // k = 1
            uint32_t af[4] = { A0.z, A1.z, A0.w, A1.w };
            #pragma unroll
            for (int nt = 0; nt < 4; nt++)
                hmma(acc[nt], af, bf[1][nt]);
        }

        // Row classes (broadcast loads) -> 8-bit masks from LUT
        int cmA = g_c1[rg0]     & 7;
        int cmB = g_c1[rg0 + 8] & 7;
        unsigned mA = (unsigned)(lut >> (cmA * 8)) & 0xFFu;
        unsigned mB = (unsigned)(lut >> (cmB * 8)) & 0xFFu;

        float va[8], vb[8];
        #pragma unroll
        for (int nt = 0; nt < 4; nt++) {
            va[2 * nt]     = (mA & (1u << (2 * nt)))     ? acc[nt][0] : 0.0f;
            va[2 * nt + 1] = (mA & (1u << (2 * nt + 1))) ? acc[nt][1] : 0.0f;
            vb[2 * nt]     = (mB & (1u << (2 * nt)))     ? acc[nt][2] : 0.0f;
            vb[2 * nt + 1] = (mB & (1u << (2 * nt + 1))) ? acc[nt][3] : 0.0f;
        }
        stg256(rowPtrA, va);
        stg256(rowPtrB, vb);
        rowPtrA += stepOut;
        rowPtrB += stepOut;
    }
}

// ----------------------------------------------------------------------------
extern "C" void kernel_launch(void* const* d_in, const int* in_sizes, int n_in,
                              void* d_out, int out_size)
{
    const float* edges1 = (const float*)d_in[0];
    const float* edges2 = (const float*)d_in[1];
    const float* W1     = (const float*)d_in[2];
    const float* b1     = (const float*)d_in[3];
    const float* W2     = (const float*)d_in[4];
    const float* b2     = (const float*)d_in[5];
    float* out = (float*)d_out;

    int N1 = in_sizes[0] / 4;
    int N2 = in_sizes[1] / 4;

    int totalThreads = (N1 + N2) * 4;
    feat_kernel<<<(totalThreads + 255) / 256, 256>>>(edges1, edges2, N1, N2, W1, b1, W2, b2);

    dim3 grid(N2 / 128, N1 / (32 * IT));
    pair_kernel<<<grid, 256>>>(out, N2);
}

// round 14
// speedup vs baseline: 1.0528x; 1.0158x over previous
#include <cuda_runtime.h>
#include <cuda_fp16.h>
#include <cstdint>

// ============================================================================
// EdgeMLP: f = MLP(edges[:, :3]); out[i][j] = (cls1[i]==cls2[j]) * cos(f1[i],f2[j])
// Round 14: R13 + software-pipelined A loads (explicit double buffer) and
// strip-prologue class preload (packed 4-bit). launch_bounds(256,3) to give
// ptxas the +8 registers the pipeline needs.
// ============================================================================

#define N_MAX 8192
#define KK 32

__device__ __half g_h1[N_MAX * KK];   // A features, per-row u32-permuted
__device__ __half g_h2[N_MAX * KK];   // B features, natural layout
__device__ int    g_c1[N_MAX];
__device__ int    g_c2[N_MAX];

// ----------------------------------------------------------------------------
// Kernel 1: MLP + normalize, 4 threads per row (each 8 of 32 outputs).
// A-side rows are written u32-permuted: orig u32 j -> pos 4*(j%4) + j/4.
// ----------------------------------------------------------------------------
__global__ void __launch_bounds__(256) feat_kernel(
    const float* __restrict__ e1, const float* __restrict__ e2, int N1, int N2,
    const float* __restrict__ W1, const float* __restrict__ b1,
    const float* __restrict__ W2, const float* __restrict__ b2)
{
    __shared__ float sW1[192], sb1[64], sW2[2048], sb2[32];
    int t = threadIdx.x;
    for (int i = t; i < 192;  i += 256) sW1[i] = W1[i];
    if (t < 64) sb1[t] = b1[t];
    for (int i = t; i < 2048; i += 256) sW2[i] = W2[i];
    if (t < 32) sb2[t] = b2[t];
    __syncthreads();

    int gid  = blockIdx.x * 256 + t;
    int row2 = gid >> 2;
    int s    = gid & 3;
    if (row2 >= N1 + N2) return;

    bool isA = (row2 < N1);
    const float* ed = isA ? e1 : e2;
    int row = isA ? row2 : row2 - N1;

    float4 e = reinterpret_cast<const float4*>(ed)[row];

    float f[8];
    #pragma unroll
    for (int q = 0; q < 8; q++) f[q] = sb2[s * 8 + q];

    #pragma unroll 8
    for (int k = 0; k < 64; k++) {
        float h = fmaf(e.x, sW1[k], fmaf(e.y, sW1[64 + k], fmaf(e.z, sW1[128 + k], sb1[k])));
        h = fmaxf(h, 0.0f);
        const float4* w = reinterpret_cast<const float4*>(&sW2[k * 32 + s * 8]);
        float4 w0 = w[0], w1 = w[1];
        f[0] = fmaf(h, w0.x, f[0]); f[1] = fmaf(h, w0.y, f[1]);
        f[2] = fmaf(h, w0.z, f[2]); f[3] = fmaf(h, w0.w, f[3]);
        f[4] = fmaf(h, w1.x, f[4]); f[5] = fmaf(h, w1.y, f[5]);
        f[6] = fmaf(h, w1.z, f[6]); f[7] = fmaf(h, w1.w, f[7]);
    }

    float p = 0.0f;
    #pragma unroll
    for (int q = 0; q < 8; q++) p = fmaf(f[q], f[q], p);
    p += __shfl_xor_sync(0xFFFFFFFFu, p, 1);
    p += __shfl_xor_sync(0xFFFFFFFFu, p, 2);
    float inv = rsqrtf(fmaxf(p, 1e-24f));

    uint32_t o[4];
    #pragma unroll
    for (int q = 0; q < 4; q++) {
        __half2 h2 = __floats2half2_rn(f[2 * q] * inv, f[2 * q + 1] * inv);
        o[q] = *reinterpret_cast<uint32_t*>(&h2);
    }

    if (isA) {
        // this thread holds original u32s j = 4s + i; dest pos = 4i + s
        uint32_t* dst = reinterpret_cast<uint32_t*>(g_h1) + (size_t)row * 16;
        #pragma unroll
        for (int i = 0; i < 4; i++) dst[4 * i + s] = o[i];
        if (s == 0) g_c1[row] = (int)e.w;
    } else {
        *reinterpret_cast<uint4*>(g_h2 + (size_t)row * KK + s * 8) =
            *reinterpret_cast<uint4*>(o);
        if (s == 0) g_c2[row] = (int)e.w;
    }
}

// ----------------------------------------------------------------------------
__device__ __forceinline__ void hmma(float c[4], const uint32_t a[4], const uint32_t b[2]) {
    asm volatile(
        "mma.sync.aligned.m16n8k16.row.col.f32.f16.f16.f32 "
        "{%0,%1,%2,%3}, {%4,%5,%6,%7}, {%8,%9}, {%0,%1,%2,%3};"
        : "+f"(c[0]), "+f"(c[1]), "+f"(c[2]), "+f"(c[3])
        : "r"(a[0]), "r"(a[1]), "r"(a[2]), "r"(a[3]), "r"(b[0]), "r"(b[1]));
}

__device__ __forceinline__ void stg256(float* p, const float v[8]) {
    asm volatile(
        "st.global.v8.b32 [%0], {%1,%2,%3,%4,%5,%6,%7,%8};"
        :: "l"(p),
           "r"(__float_as_uint(v[0])), "r"(__float_as_uint(v[1])),
           "r"(__float_as_uint(v[2])), "r"(__float_as_uint(v[3])),
           "r"(__float_as_uint(v[4])), "r"(__float_as_uint(v[5])),
           "r"(__float_as_uint(v[6])), "r"(__float_as_uint(v[7]))
        : "memory");
}

__device__ __forceinline__ void cp_async16(uint32_t smem_dst, const void* gsrc) {
    asm volatile("cp.async.cg.shared.global [%0], [%1], 16;" :: "r"(smem_dst), "l"(gsrc));
}
#define CP_COMMIT() asm volatile("cp.async.commit_group;")
#define CP_WAIT0()  asm volatile("cp.async.wait_group 0;")

// B column permutation within each 32-col slab: thread q owns 8 contiguous
// global output columns, enabling masked STG.256.
__device__ __forceinline__ int bperm_row(int j) {
    int jl = j & 31;
    int r  = ((jl >> 1) & 3) * 8 + ((jl >> 3) & 3) * 2 + (jl & 1);
    return (j & ~31) + r;
}

// ----------------------------------------------------------------------------
// Kernel 2: strip of IT subtiles (32 rows x 128 cols) per CTA, barrier-free,
// software-pipelined A loads. 8 warps (2 M x 4 N), warp subtile 16x32.
// ----------------------------------------------------------------------------
#define RS 40   // smem row stride in halves (80B)
#define IT 8    // i-subtiles per CTA strip

__global__ void __launch_bounds__(256, 3) pair_kernel(float* __restrict__ out, int N2)
{
    __shared__ __half Bs[128][RS];        // B tile (permuted), read once

    int t    = threadIdx.x;
    int wid  = t >> 5;
    int lane = t & 31;
    int j0   = blockIdx.x * 128;
    int i0   = blockIdx.y * (32 * IT);

    // --- Prologue: cp.async B (permuted) ---
    #pragma unroll
    for (int p = 0; p < 2; p++) {
        int v = t + p * 256;
        int row = v >> 2, c16 = v & 3;
        uint32_t dst = (uint32_t)__cvta_generic_to_shared(&Bs[bperm_row(row)][c16 * 8]);
        cp_async16(dst, (const char*)(g_h2 + (size_t)(j0 + row) * KK) + c16 * 16);
    }
    CP_COMMIT();

    int warp_m = wid >> 2;     // 0..1
    int warp_n = wid & 3;      // 0..3
    int r4 = lane >> 2;        // 0..7
    int q  = lane & 3;         // 0..3
    int c2 = q * 2;

    // Column-class LUT: bit (c*8 + v) set iff column v's class == c.
    int cb = warp_n * 32 + 8 * q;
    unsigned long long lut = 0ULL;
    #pragma unroll
    for (int v = 0; v < 8; v++) {
        int c = g_c2[j0 + cb + v] & 7;
        lut |= 1ULL << (c * 8 + v);
    }

    // Row classes for the whole strip, packed 4-bit (removes in-loop LDGs).
    int rA = warp_m * 16 + r4;
    unsigned clsA = 0, clsB = 0;
    #pragma unroll
    for (int it = 0; it < IT; it++) {
        clsA |= (unsigned)(g_c1[i0 + it * 32 + rA]     & 7) << (4 * it);
        clsB |= (unsigned)(g_c1[i0 + it * 32 + rA + 8] & 7) << (4 * it);
    }

    CP_WAIT0();
    __syncthreads();           // the ONLY barrier

    // --- Hoist B fragments into registers (reused for all IT subtiles) ---
    uint32_t bf[2][4][2];
    #pragma unroll
    for (int k = 0; k < 2; k++) {
        int kc = c2 + k * 16;
        #pragma unroll
        for (int nt = 0; nt < 4; nt++) {
            int col = warp_n * 32 + nt * 8 + r4;
            bf[k][nt][0] = *reinterpret_cast<const uint32_t*>(&Bs[col][kc    ]);
            bf[k][nt][1] = *reinterpret_cast<const uint32_t*>(&Bs[col][kc + 8]);
        }
    }

    const uint4* aBase = reinterpret_cast<const uint4*>(g_h1)
                       + (size_t)(i0 + rA) * 4 + q;        // 4 uint4 per row
    float* rowPtrA = out + (size_t)(i0 + rA)     * (size_t)N2 + (size_t)(j0 + cb);
    float* rowPtrB = out + (size_t)(i0 + rA + 8) * (size_t)N2 + (size_t)(j0 + cb);
    size_t stepOut = (size_t)32 * (size_t)N2;

    // --- Software pipeline: A for subtile 0 in flight before the loop ---
    uint4 A0 = __ldg(aBase);            // row rA
    uint4 A1 = __ldg(aBase + 8 * 4);    // row rA + 8

    #pragma unroll
    for (int it = 0; it < IT; it++) {
        // Prefetch A(it+1) before consuming A(it)
        uint4 A0n, A1n;
        if (it < IT - 1) {
            const uint4* nb = aBase + (size_t)(it + 1) * 32 * 4;
            A0n = __ldg(nb);
            A1n = __ldg(nb + 8 * 4);
        }

        float acc[4][4];
        #pragma unroll
        for (int nt = 0; nt < 4; nt++)
            #pragma unroll
            for (int v = 0; v < 4; v++) acc[nt][v] = 0.0f;

        {   // k = 0: af = {(rA,kc),(rA+8,kc),(rA,kc+8),(rA+8,kc+8)}
            uint32_t af[4] = { A0.x, A1.x, A0.y, A1.y };
            #pragma unroll
            for (int nt = 0; nt < 4; nt++)
                hmma(acc[nt], af, bf[0][nt]);
        }
        {   // k = 1
            uint32_t af[4] = { A0.z, A1.z, A0.w, A1.w };
            #pragma unroll
            for (int nt = 0; nt < 4; nt++)
                hmma(acc[nt], af, bf[1][nt]);
        }

        // Row classes from packed registers (ALU only)
        unsigned mA = (unsigned)(lut >> (((clsA >> (4 * it)) & 7u) * 8)) & 0xFFu;
        unsigned mB = (unsigned)(lut >> (((clsB >> (4 * it)) & 7u) * 8)) & 0xFFu;

        float va[8], vb[8];
        #pragma unroll
        for (int nt = 0; nt < 4; nt++) {
            va[2 * nt]     = (mA & (1u << (2 * nt)))     ? acc[nt][0] : 0.0f;
            va[2 * nt + 1] = (mA & (1u << (2 * nt + 1))) ? acc[nt][1] : 0.0f;
            vb[2 * nt]     = (mB & (1u << (2 * nt)))     ? acc[nt][2] : 0.0f;
            vb[2 * nt + 1] = (mB & (1u << (2 * nt + 1))) ? acc[nt][3] : 0.0f;
        }
        stg256(rowPtrA, va);
        stg256(rowPtrB, vb);
        rowPtrA += stepOut;
        rowPtrB += stepOut;

        A0 = A0n;
        A1 = A1n;
    }
}

// ----------------------------------------------------------------------------
extern "C" void kernel_launch(void* const* d_in, const int* in_sizes, int n_in,
                              void* d_out, int out_size)
{
    const float* edges1 = (const float*)d_in[0];
    const float* edges2 = (const float*)d_in[1];
    const float* W1     = (const float*)d_in[2];
    const float* b1     = (const float*)d_in[3];
    const float* W2     = (const float*)d_in[4];
    const float* b2     = (const float*)d_in[5];
    float* out = (float*)d_out;

    int N1 = in_sizes[0] / 4;
    int N2 = in_sizes[1] / 4;

    int totalThreads = (N1 + N2) * 4;
    feat_kernel<<<(totalThreads + 255) / 256, 256>>>(edges1, edges2, N1, N2, W1, b1, W2, b2);

    dim3 grid(N2 / 128, N1 / (32 * IT));
    pair_kernel<<<grid, 256>>>(out, N2);
}